// round 14
// baseline (speedup 1.0000x reference)
#include <cuda_runtime.h>
#include <cuda_fp16.h>
#include <math.h>
#include <stdint.h>

// ---------------------------------------------------------------------------
// MSDeformableAttention — GB300 (plain sm_103 target: tcgen05 unavailable)
//
//   0) wtrans_h: vp_w [K,N] fp32 -> Bh [N,K] fp16 (tiny prep, ~2us)
//   1) hgemm:    v    = value @ vp_w + vp_b   (fp16 mma.m16n8k16) -> V
//   2) tf32_gemm: soaw = query @ [so_w | aw_w] + bias             -> SOAW
//   3) sample: in-warp softmax + bilinear gather                  -> ACC
//   4) tf32_gemm: out = ACC @ op_w + op_b
//
// B=8, LQ=1024, LV=13294, D=256, H=8, HD=32, L=4, P=4
// levels (h=w,start): (100,0) (50,10000) (25,12500) (13,13125)
// ---------------------------------------------------------------------------

namespace cfg {
constexpr int B  = 8;
constexpr int LQ = 1024;
constexpr int LV = 13294;
constexpr int D  = 256;
constexpr int H  = 8;

constexpr size_t SZ_V    = (size_t)B * LV * D;      // 27,226,112
constexpr size_t SZ_SOAW = (size_t)B * LQ * 384;
constexpr size_t SZ_ACC  = (size_t)B * LQ * D;
constexpr size_t SZ_WH   = 256 * 256 / 2;           // 64K halfs in floats

constexpr size_t OFF_V    = 0;
constexpr size_t OFF_SOAW = OFF_V    + SZ_V;
constexpr size_t OFF_ACC  = OFF_SOAW + SZ_SOAW;
constexpr size_t OFF_WH   = OFF_ACC  + SZ_ACC;
constexpr size_t SZ_TOT   = OFF_WH   + SZ_WH;
}  // namespace cfg

__device__ float g_scratch[cfg::SZ_TOT];

// ---------------------------------------------------------------------------
__device__ __forceinline__ uint32_t f2tf32(float x) {
    uint32_t u;
    asm("cvt.rna.tf32.f32 %0, %1;" : "=r"(u) : "f"(x));
    return u;
}
__device__ __forceinline__ uint32_t frag_tf32(uint32_t bits) {
    return f2tf32(__uint_as_float(bits));
}

__device__ __forceinline__ void mma_tf32(float d[4], const uint32_t a[4],
                                         const uint32_t b[2]) {
    asm volatile(
        "mma.sync.aligned.m16n8k8.row.col.f32.tf32.tf32.f32 "
        "{%0,%1,%2,%3}, {%4,%5,%6,%7}, {%8,%9}, {%0,%1,%2,%3};"
        : "+f"(d[0]), "+f"(d[1]), "+f"(d[2]), "+f"(d[3])
        : "r"(a[0]), "r"(a[1]), "r"(a[2]), "r"(a[3]), "r"(b[0]), "r"(b[1]));
}

__device__ __forceinline__ void mma_f16(float d[4], const uint32_t a[4],
                                        const uint32_t b[2]) {
    asm volatile(
        "mma.sync.aligned.m16n8k16.row.col.f32.f16.f16.f32 "
        "{%0,%1,%2,%3}, {%4,%5,%6,%7}, {%8,%9}, {%0,%1,%2,%3};"
        : "+f"(d[0]), "+f"(d[1]), "+f"(d[2]), "+f"(d[3])
        : "r"(a[0]), "r"(a[1]), "r"(a[2]), "r"(a[3]), "r"(b[0]), "r"(b[1]));
}

__device__ __forceinline__ void ldsm_x4(uint32_t& r0, uint32_t& r1,
                                        uint32_t& r2, uint32_t& r3,
                                        uint32_t saddr) {
    asm volatile(
        "ldmatrix.sync.aligned.m8n8.x4.shared.b16 {%0,%1,%2,%3}, [%4];"
        : "=r"(r0), "=r"(r1), "=r"(r2), "=r"(r3) : "r"(saddr));
}

__device__ __forceinline__ void cpa16(uint32_t dst, const void* src,
                                      int src_bytes) {
    asm volatile("cp.async.cg.shared.global [%0], [%1], 16, %2;"
                 :: "r"(dst), "l"(src), "r"(src_bytes));
}
__device__ __forceinline__ void cpa4(uint32_t dst, const void* src) {
    asm volatile("cp.async.ca.shared.global [%0], [%1], 4;"
                 :: "r"(dst), "l"(src));
}
__device__ __forceinline__ void cpa_commit() {
    asm volatile("cp.async.commit_group;");
}
__device__ __forceinline__ void cpa_wait2() {
    asm volatile("cp.async.wait_group 2;");
}
__device__ __forceinline__ void cpa_wait0() {
    asm volatile("cp.async.wait_group 0;");
}

// ---------------------------------------------------------------------------
// Weight transpose+convert: out[n][k] = (half) in[k][n]   (256x256)
// ---------------------------------------------------------------------------
__global__ void wtrans_h(const float* __restrict__ in, __half* __restrict__ out)
{
    __shared__ float t[32][33];
    const int bn = blockIdx.x * 32;   // n base
    const int bk = blockIdx.y * 32;   // k base
    const int tx = threadIdx.x, ty = threadIdx.y;
#pragma unroll
    for (int i = 0; i < 32; i += 8)
        t[ty + i][tx] = in[(size_t)(bk + ty + i) * 256 + bn + tx];
    __syncthreads();
#pragma unroll
    for (int i = 0; i < 32; i += 8)
        out[(size_t)(bn + ty + i) * 256 + bk + tx] =
            __float2half_rn(t[tx][ty + i]);
}

// ---------------------------------------------------------------------------
// fp16 mma.m16n8k16 GEMM with bias:  C[M,N] = A[M,K] @ Bh[N,K]^T + bias[N]
// A fp32 gmem (converted to fp16 in the store path); Bh fp16 pre-transposed
// (cp.async). CTA 128x128, BK=32, double-buffered smem (2x16KB), 256 thr,
// 8 warps, 64x32 warp tile. Smem plane layout: plane(k16) = [128 rows][16
// halfs], 32B rows, chunk swizzle c ^= (row>>2)&1 — conflict-free for both
// ldmatrix.x4 tiles and STS.128. Requires K%32==0, N%128==0; M guarded.
// ---------------------------------------------------------------------------
__global__ __launch_bounds__(256, 2) void hgemm_bias(
    const float* __restrict__ A, const __half* __restrict__ Bh,
    const float* __restrict__ bias, float* __restrict__ C,
    int M, int N, int K)
{
    // slot: 16384B = A(2 planes x 4096) + B(2 planes x 4096)
    __shared__ __align__(128) char smh[2 * 16384];
    const uint32_t smBase = (uint32_t)__cvta_generic_to_shared(smh);

    const int tid  = threadIdx.x;
    const int wid  = tid >> 5;
    const int lane = tid & 31;
    const int row0 = blockIdx.y * 128;
    const int col0 = blockIdx.x * 128;
    const int wm   = (wid >> 2) * 64;
    const int wn   = (wid & 3) * 32;

    float acc[4][4][4];
#pragma unroll
    for (int mt = 0; mt < 4; mt++)
#pragma unroll
        for (int nt = 0; nt < 4; nt++)
#pragma unroll
            for (int r = 0; r < 4; r++) acc[mt][nt][r] = 0.0f;

    // ---- A global-load mapping: row = tid&127, plane = tid>>7 ----
    const int am  = tid & 127;
    const int apl = tid >> 7;              // which k16 plane of the stage
    const bool aok = (row0 + am) < M;
    const float* Ap = A + (size_t)(aok ? (row0 + am) : 0) * K + apl * 16;
    // A smem store offsets (both 16B chunks of plane row am)
    const int asw = (am >> 2) & 1;
    const uint32_t a_dst0 = (uint32_t)(apl * 4096 + am * 32 + ((0 ^ asw) * 16));
    const uint32_t a_dst1 = (uint32_t)(apl * 4096 + am * 32 + ((1 ^ asw) * 16));

    // ---- B cp.async mapping: 2 chunks per thread ----
    // flat = tid*2+i : c = flat&1, row = (flat>>1)&127, plane = flat>>8
    uint32_t b_dst[2];
    const __half* b_src[2];
#pragma unroll
    for (int i = 0; i < 2; i++) {
        int flat = tid * 2 + i;
        int c   = flat & 1;
        int row = (flat >> 1) & 127;
        int pl  = flat >> 8;
        b_dst[i] = (uint32_t)(8192 + pl * 4096 + row * 32 +
                              ((c ^ ((row >> 2) & 1)) * 16));
        b_src[i] = Bh + (size_t)(col0 + row) * K + pl * 16 + c * 8;
    }

    // ---- ldmatrix per-lane offsets (within a plane) ----
    uint32_t aoff[4];
#pragma unroll
    for (int mt = 0; mt < 4; mt++) {
        int row = wm + mt * 16 + ((lane >> 3) & 1) * 8 + (lane & 7);
        int c   = lane >> 4;
        aoff[mt] = (uint32_t)(row * 32 + ((c ^ ((row >> 2) & 1)) * 16));
    }
    uint32_t boff[2];
#pragma unroll
    for (int ng = 0; ng < 2; ng++) {
        int row = wn + ng * 16 + ((lane >> 4) & 1) * 8 + (lane & 7);
        int c   = (lane >> 3) & 1;
        boff[ng] = (uint32_t)(8192 + row * 32 + ((c ^ ((row >> 2) & 1)) * 16));
    }

    float4 ga[4];
    auto gloadA = [&](int stage) {
        if (aok) {
#pragma unroll
            for (int j = 0; j < 4; j++)
                ga[j] = *(const float4*)(Ap + stage * 32 + j * 4);
        } else {
#pragma unroll
            for (int j = 0; j < 4; j++)
                ga[j] = make_float4(0.f, 0.f, 0.f, 0.f);
        }
    };
    auto stsA = [&](int slot) {
        uint32_t h[8];
#pragma unroll
        for (int j = 0; j < 4; j++) {
            __half2 p0 = __floats2half2_rn(ga[j].x, ga[j].y);
            __half2 p1 = __floats2half2_rn(ga[j].z, ga[j].w);
            h[j * 2]     = *(uint32_t*)&p0;
            h[j * 2 + 1] = *(uint32_t*)&p1;
        }
        char* base = smh + slot * 16384;
        *(uint4*)(base + a_dst0) = make_uint4(h[0], h[1], h[2], h[3]);
        *(uint4*)(base + a_dst1) = make_uint4(h[4], h[5], h[6], h[7]);
    };
    auto issueB = [&](int slot, int stage) {
        const uint32_t sb = smBase + (uint32_t)slot * 16384u;
#pragma unroll
        for (int i = 0; i < 2; i++)
            cpa16(sb + b_dst[i], b_src[i] + (size_t)stage * 32, 16);
    };
    auto compute = [&](int slot) {
        const uint32_t sb = smBase + (uint32_t)slot * 16384u;
#pragma unroll
        for (int ks = 0; ks < 2; ks++) {
            const uint32_t pl = (uint32_t)ks * 4096u;
            uint32_t bfr[4][2];
#pragma unroll
            for (int ng = 0; ng < 2; ng++) {
                uint32_t r0, r1, r2, r3;
                ldsm_x4(r0, r1, r2, r3, sb + pl + boff[ng]);
                bfr[ng * 2][0]     = r0;
                bfr[ng * 2][1]     = r1;
                bfr[ng * 2 + 1][0] = r2;
                bfr[ng * 2 + 1][1] = r3;
            }
#pragma unroll
            for (int mt = 0; mt < 4; mt++) {
                uint32_t afr[4];
                ldsm_x4(afr[0], afr[1], afr[2], afr[3], sb + pl + aoff[mt]);
#pragma unroll
                for (int nt = 0; nt < 4; nt++)
                    mma_f16(acc[mt][nt], afr, bfr[nt]);
            }
        }
    };

    const int nstage = K >> 5;           // BK = 32
    gloadA(0);
    issueB(0, 0);
    cpa_commit();
    stsA(0);
    cpa_wait0();
    __syncthreads();

    for (int s = 0; s < nstage; s++) {
        if (s + 1 < nstage) {
            gloadA(s + 1);
            issueB((s + 1) & 1, s + 1);
            cpa_commit();
        }
        compute(s & 1);
        if (s + 1 < nstage) {
            stsA((s + 1) & 1);
            cpa_wait0();
            __syncthreads();
        }
    }

    // Epilogue: direct float2 stores (C fragment layout same as tf32 path)
    const int g = lane >> 2;
    const int c = lane & 3;
#pragma unroll
    for (int nt = 0; nt < 4; nt++) {
        const int cl  = wn + nt * 8 + c * 2;
        const float b0v = __ldg(bias + col0 + cl);
        const float b1v = __ldg(bias + col0 + cl + 1);
#pragma unroll
        for (int mt = 0; mt < 4; mt++) {
            const int r0 = row0 + wm + mt * 16 + g;
            if (r0 < M) {
                float2 o = make_float2(acc[mt][nt][0] + b0v, acc[mt][nt][1] + b1v);
                *(float2*)(C + (size_t)r0 * N + col0 + cl) = o;
            }
            if (r0 + 8 < M) {
                float2 o = make_float2(acc[mt][nt][2] + b0v, acc[mt][nt][3] + b1v);
                *(float2*)(C + (size_t)(r0 + 8) * N + col0 + cl) = o;
            }
        }
    }
}

// ---------------------------------------------------------------------------
// tf32 mma.sync GEMM with bias, dual B source (proven R12 kernel, unchanged)
// ---------------------------------------------------------------------------
__global__ __launch_bounds__(256, 2) void tf32_gemm_dual(
    const float* __restrict__ A,
    const float* __restrict__ B0, int ldB0,
    const float* __restrict__ B1, int ldB1, int N0,
    const float* __restrict__ bias0, const float* __restrict__ bias1,
    float* __restrict__ C, int M, int N, int K)
{
    constexpr int NSTAGE = 4;
    __shared__ uint32_t As[NSTAGE][128 * 16];
    __shared__ uint32_t Bs[NSTAGE][128 * 16];

    const int tid  = threadIdx.x;
    const int wid  = tid >> 5;
    const int lane = tid & 31;
    const int row0 = blockIdx.y * 128;
    const int col0 = blockIdx.x * 128;
    const int wm   = (wid >> 2) * 64;
    const int wn   = (wid & 3) * 32;

    const bool sel = (col0 >= N0);
    const float* Bbase = sel ? (B1 + (col0 - N0)) : (B0 + col0);
    const int    ldB   = sel ? ldB1 : ldB0;
    const float* biasp = sel ? (bias1 + (col0 - N0)) : (bias0 + col0);

    float acc[4][4][4];
#pragma unroll
    for (int mt = 0; mt < 4; mt++)
#pragma unroll
        for (int nt = 0; nt < 4; nt++)
#pragma unroll
            for (int r = 0; r < 4; r++) acc[mt][nt][r] = 0.0f;

    const int ar = tid >> 1;
    const int ak = (tid & 1) * 8;
    const bool aok = (row0 + ar) < M;
    const int a_srcb = aok ? 16 : 0;
    const float* Ap = A + (size_t)(aok ? (row0 + ar) : 0) * K + ak;
    const int bn  = tid & 127;
    const int bkh = (tid >> 7) * 8;

    const int a_sw  = (ar >> 1) & 3;
    const int a_c0  = ak >> 2;
    const uint32_t a_off0 = ar * 16 + ((a_c0 ^ a_sw) << 2);
    const uint32_t a_off1 = ar * 16 + (((a_c0 + 1) ^ a_sw) << 2);
    const int b_sw  = (bn >> 1) & 3;
    const int b_c0  = bkh >> 2;
    const uint32_t b_off0 = bn * 16 + ((b_c0 ^ b_sw) << 2);
    const uint32_t b_off1 = bn * 16 + (((b_c0 + 1) ^ b_sw) << 2);

    const uint32_t asBase = (uint32_t)__cvta_generic_to_shared(As);
    const uint32_t bsBase = (uint32_t)__cvta_generic_to_shared(Bs);

    int a_mrow[4], a_msw[4];
#pragma unroll
    for (int mt = 0; mt < 4; mt++) {
        a_mrow[mt] = wm + mt * 16 + (lane & 7) + ((lane >> 3) & 1) * 8;
        a_msw[mt]  = (a_mrow[mt] >> 1) & 3;
    }
    const int a_cadd = lane >> 4;
    int b_nrow[2], b_nsw[2];
#pragma unroll
    for (int p = 0; p < 2; p++) {
        b_nrow[p] = wn + p * 16 + (lane & 7) + ((lane >> 4) & 1) * 8;
        b_nsw[p]  = (b_nrow[p] >> 1) & 3;
    }
    const int b_cadd = (lane >> 3) & 1;

    auto issue_copy = [&](int slot, int kbase) {
        const uint32_t aslot = asBase + (uint32_t)slot * 8192u;
        const uint32_t bslot = bsBase + (uint32_t)slot * 8192u;
        cpa16(aslot + a_off0 * 4u, Ap + kbase, a_srcb);
        cpa16(aslot + a_off1 * 4u, Ap + kbase + 4, a_srcb);
        const float* bp = Bbase + (size_t)(kbase + bkh) * ldB + bn;
#pragma unroll
        for (int i = 0; i < 4; i++)
            cpa4(bslot + (b_off0 + i) * 4u, bp + (size_t)i * ldB);
#pragma unroll
        for (int i = 0; i < 4; i++)
            cpa4(bslot + (b_off1 + i) * 4u, bp + (size_t)(i + 4) * ldB);
    };

    auto compute = [&](int buf) {
        const uint32_t aslot = asBase + (uint32_t)buf * 8192u;
        const uint32_t bslot = bsBase + (uint32_t)buf * 8192u;
#pragma unroll
        for (int ks = 0; ks < 2; ks++) {
            const int cb = ks * 2;
            uint32_t bfr[4][2];
#pragma unroll
            for (int p = 0; p < 2; p++) {
                uint32_t w = (uint32_t)(b_nrow[p] * 16 +
                                        (((cb + b_cadd) ^ b_nsw[p]) << 2));
                uint32_t r0, r1, r2, r3;
                ldsm_x4(r0, r1, r2, r3, bslot + w * 4u);
                bfr[p * 2][0]     = frag_tf32(r0);
                bfr[p * 2][1]     = frag_tf32(r1);
                bfr[p * 2 + 1][0] = frag_tf32(r2);
                bfr[p * 2 + 1][1] = frag_tf32(r3);
            }
#pragma unroll
            for (int mt = 0; mt < 4; mt++) {
                uint32_t w = (uint32_t)(a_mrow[mt] * 16 +
                                        (((cb + a_cadd) ^ a_msw[mt]) << 2));
                uint32_t afr[4];
                ldsm_x4(afr[0], afr[1], afr[2], afr[3], aslot + w * 4u);
                afr[0] = frag_tf32(afr[0]);
                afr[1] = frag_tf32(afr[1]);
                afr[2] = frag_tf32(afr[2]);
                afr[3] = frag_tf32(afr[3]);
#pragma unroll
                for (int nt = 0; nt < 4; nt++)
                    mma_tf32(acc[mt][nt], afr, bfr[nt]);
            }
        }
    };

    const int nstage = K >> 4;
#pragma unroll
    for (int s = 0; s < 3; s++) {
        if (s < nstage) issue_copy(s, s << 4);
        cpa_commit();
    }
    cpa_wait2();
    __syncthreads();

    for (int s = 0; s < nstage; s++) {
        if (s + 3 < nstage) issue_copy((s + 3) & 3, (s + 3) << 4);
        cpa_commit();
        compute(s & 3);
        cpa_wait2();
        __syncthreads();
    }

    const int g = lane >> 2;
    const int c = lane & 3;
#pragma unroll
    for (int nt = 0; nt < 4; nt++) {
        const int cl  = wn + nt * 8 + c * 2;
        const float b0v = __ldg(biasp + cl);
        const float b1v = __ldg(biasp + cl + 1);
#pragma unroll
        for (int mt = 0; mt < 4; mt++) {
            const int r0 = row0 + wm + mt * 16 + g;
            if (r0 < M) {
                float2 o = make_float2(acc[mt][nt][0] + b0v, acc[mt][nt][1] + b1v);
                *(float2*)(C + (size_t)r0 * N + col0 + cl) = o;
            }
            if (r0 + 8 < M) {
                float2 o = make_float2(acc[mt][nt][2] + b0v, acc[mt][nt][3] + b1v);
                *(float2*)(C + (size_t)(r0 + 8) * N + col0 + cl) = o;
            }
        }
    }
}

// ---------------------------------------------------------------------------
// Sampling + in-warp softmax: one warp per (b, q, h); two 16-lane halves each
// handle one point of a pair; lanes carry 2 channels (float2).
// ---------------------------------------------------------------------------
__global__ __launch_bounds__(256) void sample_kernel(
    const float* __restrict__ ref,    // [B, LQ, 4, 2]
    const float* __restrict__ v,      // [B, LV, H, HD]
    const float* __restrict__ soaw,   // [B*LQ, 384]
    float* __restrict__ acc_out)      // [B*LQ, 256]
{
    const int w    = blockIdx.x * 8 + (threadIdx.x >> 5);
    const int lane = threadIdx.x & 31;
    const int h    = w & 7;
    const int bq   = w >> 3;
    const int b    = bq >> 10;

    const int half = lane >> 4;
    const int ch   = (lane & 15) * 2;

    const float*  row  = soaw + (size_t)bq * 384;
    const float2* so2  = (const float2*)(row + h * 32);
    const float*  aw_p = row + 256 + h * 16;
    const float*  ref_p = ref + (size_t)bq * 8;
    const float*  vb   = v + (size_t)b * cfg::LV * cfg::D + h * 32 + ch;

    float logit = (lane < 16) ? aw_p[lane] : -1e30f;
    float mx = logit;
#pragma unroll
    for (int off = 8; off >= 1; off >>= 1)
        mx = fmaxf(mx, __shfl_xor_sync(0xffffffffu, mx, off));
    float e = __expf(logit - mx);
    float ssum = e;
#pragma unroll
    for (int off = 8; off >= 1; off >>= 1)
        ssum += __shfl_xor_sync(0xffffffffu, ssum, off);
    const float wnorm = e / ssum;

    const int LHW[4]    = {100, 50, 25, 13};
    const int LSTART[4] = {0, 10000, 12500, 13125};

    float2 acc2 = make_float2(0.f, 0.f);
#pragma unroll
    for (int l = 0; l < 4; l++) {
        const int   Wl = LHW[l];
        const int   Hl = LHW[l];
        const float bx = ref_p[l * 2 + 0] * (float)Wl - 0.5f;
        const float by = ref_p[l * 2 + 1] * (float)Hl - 0.5f;
        const float* base = vb + (size_t)LSTART[l] * cfg::D;

#pragma unroll
        for (int pp = 0; pp < 2; pp++) {
            const int   idx = l * 4 + pp * 2 + half;
            const float2 so = so2[idx];
            const float x   = bx + so.x;
            const float y   = by + so.y;
            const float wt  = __shfl_sync(0xffffffffu, wnorm, idx);

            const float x0f = floorf(x), y0f = floorf(y);
            const int   ix0 = (int)x0f,  iy0 = (int)y0f;
            const float fx = x - x0f,    fy = y - y0f;

            const bool vx0 = (ix0 >= 0)     && (ix0 < Wl);
            const bool vx1 = (ix0 + 1 >= 0) && (ix0 + 1 < Wl);
            const bool vy0 = (iy0 >= 0)     && (iy0 < Hl);
            const bool vy1 = (iy0 + 1 >= 0) && (iy0 + 1 < Hl);

            float2 v00 = make_float2(0.f, 0.f), v01 = v00;
            float2 v10 = v00, v11 = v00;
            if (vy0) {
                const float* r0 = base + (size_t)(iy0 * Wl) * cfg::D;
                if (vx0) v00 = *(const float2*)(r0 + (size_t)ix0 * cfg::D);
                if (vx1) v01 = *(const float2*)(r0 + (size_t)(ix0 + 1) * cfg::D);
            }
            if (vy1) {
                const float* r1 = base + (size_t)((iy0 + 1) * Wl) * cfg::D;
                if (vx0) v10 = *(const float2*)(r1 + (size_t)ix0 * cfg::D);
                if (vx1) v11 = *(const float2*)(r1 + (size_t)(ix0 + 1) * cfg::D);
            }

            const float w00 = (1.f - fx) * (1.f - fy);
            const float w01 = fx * (1.f - fy);
            const float w10 = (1.f - fx) * fy;
            const float w11 = fx * fy;

            acc2.x = fmaf(wt, v00.x * w00 + v01.x * w01 +
                              v10.x * w10 + v11.x * w11, acc2.x);
            acc2.y = fmaf(wt, v00.y * w00 + v01.y * w01 +
                              v10.y * w10 + v11.y * w11, acc2.y);
        }
    }

    acc2.x += __shfl_xor_sync(0xffffffffu, acc2.x, 16);
    acc2.y += __shfl_xor_sync(0xffffffffu, acc2.y, 16);
    if (lane < 16)
        *(float2*)(acc_out + (size_t)bq * 256 + h * 32 + ch) = acc2;
}

// ---------------------------------------------------------------------------
// Launch
// ---------------------------------------------------------------------------
extern "C" void kernel_launch(void* const* d_in, const int* in_sizes, int n_in,
                              void* d_out, int out_size)
{
    const float* query = (const float*)d_in[0];   // [8,1024,256]
    const float* refp  = (const float*)d_in[1];   // [8,1024,4,2]
    const float* value = (const float*)d_in[2];   // [8,13294,256]
    // d_in[3] = value_spatial_shapes (compile-time constant)
    const float* so_w  = (const float*)d_in[4];   // [256,256]  [K,N]
    const float* so_b  = (const float*)d_in[5];
    const float* aw_w  = (const float*)d_in[6];   // [256,128]  [K,N]
    const float* aw_b  = (const float*)d_in[7];
    const float* vp_w  = (const float*)d_in[8];   // [256,256]  [K,N]
    const float* vp_b  = (const float*)d_in[9];
    const float* op_w  = (const float*)d_in[10];  // [256,256]  [K,N]
    const float* op_b  = (const float*)d_in[11];
    float* out = (float*)d_out;                   // [8,1024,256]

    float* scratch = nullptr;
    cudaGetSymbolAddress((void**)&scratch, g_scratch);
    float*  sV    = scratch + cfg::OFF_V;
    float*  sSOAW = scratch + cfg::OFF_SOAW;
    float*  sACC  = scratch + cfg::OFF_ACC;
    __half* sWH   = (__half*)(scratch + cfg::OFF_WH);

    const int MQ = cfg::B * cfg::LQ;      // 8192
    const int MV = cfg::B * cfg::LV;      // 106352

    // 0) vp_w -> fp16 [N,K]
    wtrans_h<<<dim3(8, 8), dim3(32, 8)>>>(vp_w, sWH);
    // 1) v = value @ vp_w + vp_b   (fp16 tensor path)
    hgemm_bias<<<dim3(2, (MV + 127) / 128), 256>>>(
        value, sWH, vp_b, sV, MV, 256, 256);
    // 2) soaw = query @ [so_w | aw_w] + [so_b | aw_b]  (split at col 256)
    tf32_gemm_dual<<<dim3(3, MQ / 128), 256>>>(
        query, so_w, 256, aw_w, 128, 256, so_b, aw_b, sSOAW, MQ, 384, 256);
    // 3) sampling (softmax folded in; 2 points per warp, float2 lanes)
    {
        int warps = cfg::B * cfg::LQ * cfg::H;   // 65536
        sample_kernel<<<warps / 8, 256>>>(refp, sV, sSOAW, sACC);
    }
    // 4) out = ACC @ op_w + op_b
    tf32_gemm_dual<<<dim3(2, MQ / 128), 256>>>(
        sACC, op_w, 256, op_w, 256, 256, op_b, op_b, out, MQ, 256, 256);
}

// round 15
// speedup vs baseline: 1.0827x; 1.0827x over previous
#include <cuda_runtime.h>
#include <math.h>
#include <stdint.h>

// ---------------------------------------------------------------------------
// MSDeformableAttention — GB300 (plain sm_103 target: tcgen05 unavailable,
// legacy mma.sync tf32 tensor path, ldmatrix fragment loads,
// cp.async 4-stage smem pipeline; sample kernel: per-point geometry
// broadcast via shfl, branch-free clamped gathers)
//
//   1) tf32_gemm: v    = value @ vp_w + vp_b            -> V [B*LV, 256]
//   2) tf32_gemm: soaw = query @ [so_w | aw_w] + bias   -> SOAW [B*LQ, 384]
//   3) sample: in-warp softmax + bilinear gather        -> ACC [B*LQ, 256]
//   4) tf32_gemm: out = ACC @ op_w + op_b
//
// B=8, LQ=1024, LV=13294, D=256, H=8, HD=32, L=4, P=4
// levels (h=w,start): (100,0) (50,10000) (25,12500) (13,13125)
// ---------------------------------------------------------------------------

namespace cfg {
constexpr int B  = 8;
constexpr int LQ = 1024;
constexpr int LV = 13294;
constexpr int D  = 256;
constexpr int H  = 8;

constexpr size_t SZ_V    = (size_t)B * LV * D;      // 27,226,112
constexpr size_t SZ_SOAW = (size_t)B * LQ * 384;
constexpr size_t SZ_ACC  = (size_t)B * LQ * D;

constexpr size_t OFF_V    = 0;
constexpr size_t OFF_SOAW = OFF_V    + SZ_V;
constexpr size_t OFF_ACC  = OFF_SOAW + SZ_SOAW;
constexpr size_t SZ_TOT   = OFF_ACC  + SZ_ACC;      // ~32.5M floats (~130 MB)
}  // namespace cfg

__device__ float g_scratch[cfg::SZ_TOT];

// ---------------------------------------------------------------------------
__device__ __forceinline__ uint32_t f2tf32(float x) {
    uint32_t u;
    asm("cvt.rna.tf32.f32 %0, %1;" : "=r"(u) : "f"(x));
    return u;
}
__device__ __forceinline__ uint32_t frag_tf32(uint32_t bits) {
    return f2tf32(__uint_as_float(bits));
}

__device__ __forceinline__ void mma_tf32(float d[4], const uint32_t a[4],
                                         const uint32_t b[2]) {
    asm volatile(
        "mma.sync.aligned.m16n8k8.row.col.f32.tf32.tf32.f32 "
        "{%0,%1,%2,%3}, {%4,%5,%6,%7}, {%8,%9}, {%0,%1,%2,%3};"
        : "+f"(d[0]), "+f"(d[1]), "+f"(d[2]), "+f"(d[3])
        : "r"(a[0]), "r"(a[1]), "r"(a[2]), "r"(a[3]), "r"(b[0]), "r"(b[1]));
}

__device__ __forceinline__ void ldsm_x4(uint32_t& r0, uint32_t& r1,
                                        uint32_t& r2, uint32_t& r3,
                                        uint32_t saddr) {
    asm volatile(
        "ldmatrix.sync.aligned.m8n8.x4.shared.b16 {%0,%1,%2,%3}, [%4];"
        : "=r"(r0), "=r"(r1), "=r"(r2), "=r"(r3) : "r"(saddr));
}

__device__ __forceinline__ void cpa16(uint32_t dst, const void* src,
                                      int src_bytes) {
    asm volatile("cp.async.cg.shared.global [%0], [%1], 16, %2;"
                 :: "r"(dst), "l"(src), "r"(src_bytes));
}
__device__ __forceinline__ void cpa4(uint32_t dst, const void* src) {
    asm volatile("cp.async.ca.shared.global [%0], [%1], 4;"
                 :: "r"(dst), "l"(src));
}
__device__ __forceinline__ void cpa_commit() {
    asm volatile("cp.async.commit_group;");
}
__device__ __forceinline__ void cpa_wait2() {
    asm volatile("cp.async.wait_group 2;");
}

// ---------------------------------------------------------------------------
// tf32 mma.sync GEMM with bias, dual B source (proven R12 kernel, unchanged):
//   C[M,N] = A[M,K] @ B[K,N] + bias[N]
// ---------------------------------------------------------------------------
__global__ __launch_bounds__(256, 2) void tf32_gemm_dual(
    const float* __restrict__ A,
    const float* __restrict__ B0, int ldB0,
    const float* __restrict__ B1, int ldB1, int N0,
    const float* __restrict__ bias0, const float* __restrict__ bias1,
    float* __restrict__ C, int M, int N, int K)
{
    constexpr int NSTAGE = 4;
    __shared__ uint32_t As[NSTAGE][128 * 16];
    __shared__ uint32_t Bs[NSTAGE][128 * 16];

    const int tid  = threadIdx.x;
    const int wid  = tid >> 5;
    const int lane = tid & 31;
    const int row0 = blockIdx.y * 128;
    const int col0 = blockIdx.x * 128;
    const int wm   = (wid >> 2) * 64;
    const int wn   = (wid & 3) * 32;

    const bool sel = (col0 >= N0);
    const float* Bbase = sel ? (B1 + (col0 - N0)) : (B0 + col0);
    const int    ldB   = sel ? ldB1 : ldB0;
    const float* biasp = sel ? (bias1 + (col0 - N0)) : (bias0 + col0);

    float acc[4][4][4];
#pragma unroll
    for (int mt = 0; mt < 4; mt++)
#pragma unroll
        for (int nt = 0; nt < 4; nt++)
#pragma unroll
            for (int r = 0; r < 4; r++) acc[mt][nt][r] = 0.0f;

    const int ar = tid >> 1;
    const int ak = (tid & 1) * 8;
    const bool aok = (row0 + ar) < M;
    const int a_srcb = aok ? 16 : 0;
    const float* Ap = A + (size_t)(aok ? (row0 + ar) : 0) * K + ak;
    const int bn  = tid & 127;
    const int bkh = (tid >> 7) * 8;

    const int a_sw  = (ar >> 1) & 3;
    const int a_c0  = ak >> 2;
    const uint32_t a_off0 = ar * 16 + ((a_c0 ^ a_sw) << 2);
    const uint32_t a_off1 = ar * 16 + (((a_c0 + 1) ^ a_sw) << 2);
    const int b_sw  = (bn >> 1) & 3;
    const int b_c0  = bkh >> 2;
    const uint32_t b_off0 = bn * 16 + ((b_c0 ^ b_sw) << 2);
    const uint32_t b_off1 = bn * 16 + (((b_c0 + 1) ^ b_sw) << 2);

    const uint32_t asBase = (uint32_t)__cvta_generic_to_shared(As);
    const uint32_t bsBase = (uint32_t)__cvta_generic_to_shared(Bs);

    int a_mrow[4], a_msw[4];
#pragma unroll
    for (int mt = 0; mt < 4; mt++) {
        a_mrow[mt] = wm + mt * 16 + (lane & 7) + ((lane >> 3) & 1) * 8;
        a_msw[mt]  = (a_mrow[mt] >> 1) & 3;
    }
    const int a_cadd = lane >> 4;
    int b_nrow[2], b_nsw[2];
#pragma unroll
    for (int p = 0; p < 2; p++) {
        b_nrow[p] = wn + p * 16 + (lane & 7) + ((lane >> 4) & 1) * 8;
        b_nsw[p]  = (b_nrow[p] >> 1) & 3;
    }
    const int b_cadd = (lane >> 3) & 1;

    auto issue_copy = [&](int slot, int kbase) {
        const uint32_t aslot = asBase + (uint32_t)slot * 8192u;
        const uint32_t bslot = bsBase + (uint32_t)slot * 8192u;
        cpa16(aslot + a_off0 * 4u, Ap + kbase, a_srcb);
        cpa16(aslot + a_off1 * 4u, Ap + kbase + 4, a_srcb);
        const float* bp = Bbase + (size_t)(kbase + bkh) * ldB + bn;
#pragma unroll
        for (int i = 0; i < 4; i++)
            cpa4(bslot + (b_off0 + i) * 4u, bp + (size_t)i * ldB);
#pragma unroll
        for (int i = 0; i < 4; i++)
            cpa4(bslot + (b_off1 + i) * 4u, bp + (size_t)(i + 4) * ldB);
    };

    auto compute = [&](int buf) {
        const uint32_t aslot = asBase + (uint32_t)buf * 8192u;
        const uint32_t bslot = bsBase + (uint32_t)buf * 8192u;
#pragma unroll
        for (int ks = 0; ks < 2; ks++) {
            const int cb = ks * 2;
            uint32_t bfr[4][2];
#pragma unroll
            for (int p = 0; p < 2; p++) {
                uint32_t w = (uint32_t)(b_nrow[p] * 16 +
                                        (((cb + b_cadd) ^ b_nsw[p]) << 2));
                uint32_t r0, r1, r2, r3;
                ldsm_x4(r0, r1, r2, r3, bslot + w * 4u);
                bfr[p * 2][0]     = frag_tf32(r0);
                bfr[p * 2][1]     = frag_tf32(r1);
                bfr[p * 2 + 1][0] = frag_tf32(r2);
                bfr[p * 2 + 1][1] = frag_tf32(r3);
            }
#pragma unroll
            for (int mt = 0; mt < 4; mt++) {
                uint32_t w = (uint32_t)(a_mrow[mt] * 16 +
                                        (((cb + a_cadd) ^ a_msw[mt]) << 2));
                uint32_t afr[4];
                ldsm_x4(afr[0], afr[1], afr[2], afr[3], aslot + w * 4u);
                afr[0] = frag_tf32(afr[0]);
                afr[1] = frag_tf32(afr[1]);
                afr[2] = frag_tf32(afr[2]);
                afr[3] = frag_tf32(afr[3]);
#pragma unroll
                for (int nt = 0; nt < 4; nt++)
                    mma_tf32(acc[mt][nt], afr, bfr[nt]);
            }
        }
    };

    const int nstage = K >> 4;
#pragma unroll
    for (int s = 0; s < 3; s++) {
        if (s < nstage) issue_copy(s, s << 4);
        cpa_commit();
    }
    cpa_wait2();
    __syncthreads();

    for (int s = 0; s < nstage; s++) {
        if (s + 3 < nstage) issue_copy((s + 3) & 3, (s + 3) << 4);
        cpa_commit();
        compute(s & 3);
        cpa_wait2();
        __syncthreads();
    }

    const int g = lane >> 2;
    const int c = lane & 3;
#pragma unroll
    for (int nt = 0; nt < 4; nt++) {
        const int cl  = wn + nt * 8 + c * 2;
        const float b0v = __ldg(biasp + cl);
        const float b1v = __ldg(biasp + cl + 1);
#pragma unroll
        for (int mt = 0; mt < 4; mt++) {
            const int r0 = row0 + wm + mt * 16 + g;
            if (r0 < M) {
                float2 o = make_float2(acc[mt][nt][0] + b0v, acc[mt][nt][1] + b1v);
                *(float2*)(C + (size_t)r0 * N + col0 + cl) = o;
            }
            if (r0 + 8 < M) {
                float2 o = make_float2(acc[mt][nt][2] + b0v, acc[mt][nt][3] + b1v);
                *(float2*)(C + (size_t)(r0 + 8) * N + col0 + cl) = o;
            }
        }
    }
}

// ---------------------------------------------------------------------------
// Sampling + in-warp softmax: one warp per (b, q, h).
// Lane p = lane&15 precomputes point p's geometry ONCE: 4 clamped corner
// offsets (int, in floats) + 4 weights premultiplied by softmax-wt and
// validity (invalid corner -> weight 0, address clamped so the load is
// always in-bounds). Main loop is branch-free: two 16-lane halves each
// handle one point of a pair; 8 shfl broadcasts + 4 float2 loads + 8 FMA
// per iteration; lanes carry 2 channels.
// SOAW row layout: [so (256) | aw logits (128)]  stride 384.
// ---------------------------------------------------------------------------
__global__ __launch_bounds__(256) void sample_kernel(
    const float* __restrict__ ref,    // [B, LQ, 4, 2]
    const float* __restrict__ v,      // [B, LV, H, HD]
    const float* __restrict__ soaw,   // [B*LQ, 384]
    float* __restrict__ acc_out)      // [B*LQ, 256]
{
    const int w    = blockIdx.x * 8 + (threadIdx.x >> 5);
    const int lane = threadIdx.x & 31;
    const int h    = w & 7;
    const int bq   = w >> 3;
    const int b    = bq >> 10;

    const int half = lane >> 4;        // which point of a pair
    const int ch   = (lane & 15) * 2;  // channel pair
    const int p    = lane & 15;        // geometry point owned by this lane

    const float*  row   = soaw + (size_t)bq * 384;
    const float2* so2   = (const float2*)(row + h * 32);
    const float*  aw_p  = row + 256 + h * 16;
    const float*  ref_p = ref + (size_t)bq * 8;
    const float*  vb    = v + (size_t)b * (cfg::LV * cfg::D) + h * 32 + ch;

    // --- softmax over 16 logits (xor reductions within 16-lane halves) ---
    float logit = (lane < 16) ? aw_p[lane] : -1e30f;
    float mx = logit;
#pragma unroll
    for (int off = 8; off >= 1; off >>= 1)
        mx = fmaxf(mx, __shfl_xor_sync(0xffffffffu, mx, off));
    float e = __expf(logit - mx);
    float ssum = e;
#pragma unroll
    for (int off = 8; off >= 1; off >>= 1)
        ssum += __shfl_xor_sync(0xffffffffu, ssum, off);
    const float wnorm = e / ssum;                       // lanes 0..15 valid

    // --- per-point geometry (lane p; upper half duplicates lower) ---
    const int lp = p >> 2;
    const int Wl = (lp == 0) ? 100 : (lp == 1) ? 50 : (lp == 2) ? 25 : 13;
    const float Wf = (float)Wl;

    const float2 so = so2[p];
    const float x = fmaf(ref_p[lp * 2 + 0], Wf, -0.5f) + so.x;
    const float y = fmaf(ref_p[lp * 2 + 1], Wf, -0.5f) + so.y;

    const float x0f = floorf(x), y0f = floorf(y);
    const int   ix0 = (int)x0f,  iy0 = (int)y0f;
    const float fx = x - x0f,    fy = y - y0f;

    const float wt = __shfl_sync(0xffffffffu, wnorm, p);

    const bool vx0 = (unsigned)ix0       < (unsigned)Wl;
    const bool vx1 = (unsigned)(ix0 + 1) < (unsigned)Wl;
    const bool vy0 = (unsigned)iy0       < (unsigned)Wl;
    const bool vy1 = (unsigned)(iy0 + 1) < (unsigned)Wl;

    const float gx0 = vx0 ? (1.f - fx) : 0.f;
    const float gx1 = vx1 ? fx         : 0.f;
    const float gy0 = vy0 ? wt * (1.f - fy) : 0.f;
    const float gy1 = vy1 ? wt * fy         : 0.f;

    const float my_w00 = gx0 * gy0, my_w01 = gx1 * gy0;
    const float my_w10 = gx0 * gy1, my_w11 = gx1 * gy1;

    const int cx0 = min(max(ix0, 0), Wl - 1);
    const int cx1 = min(max(ix0 + 1, 0), Wl - 1);
    const int cy0 = min(max(iy0, 0), Wl - 1);
    const int cy1 = min(max(iy0 + 1, 0), Wl - 1);
    const int rA = cy0 * Wl, rB = cy1 * Wl;
    const int my_o00 = (rA + cx0) * 256, my_o01 = (rA + cx1) * 256;
    const int my_o10 = (rB + cx0) * 256, my_o11 = (rB + cx1) * 256;

    // --- branch-free gather loop ---
    const int LSTART[4] = {0, 10000, 12500, 13125};

    float2 acc2 = make_float2(0.f, 0.f);
#pragma unroll
    for (int l = 0; l < 4; l++) {
        const float* base = vb + (size_t)LSTART[l] * cfg::D;
#pragma unroll
        for (int pp = 0; pp < 2; pp++) {
            const int idx = l * 4 + pp * 2 + half;
            const int o00 = __shfl_sync(0xffffffffu, my_o00, idx);
            const int o01 = __shfl_sync(0xffffffffu, my_o01, idx);
            const int o10 = __shfl_sync(0xffffffffu, my_o10, idx);
            const int o11 = __shfl_sync(0xffffffffu, my_o11, idx);
            const float w00 = __shfl_sync(0xffffffffu, my_w00, idx);
            const float w01 = __shfl_sync(0xffffffffu, my_w01, idx);
            const float w10 = __shfl_sync(0xffffffffu, my_w10, idx);
            const float w11 = __shfl_sync(0xffffffffu, my_w11, idx);

            const float2 v00 = *(const float2*)(base + o00);
            const float2 v01 = *(const float2*)(base + o01);
            const float2 v10 = *(const float2*)(base + o10);
            const float2 v11 = *(const float2*)(base + o11);

            acc2.x += v00.x * w00 + v01.x * w01 + v10.x * w10 + v11.x * w11;
            acc2.y += v00.y * w00 + v01.y * w01 + v10.y * w10 + v11.y * w11;
        }
    }

    // merge the two half-warp partials (channels identical across halves)
    acc2.x += __shfl_xor_sync(0xffffffffu, acc2.x, 16);
    acc2.y += __shfl_xor_sync(0xffffffffu, acc2.y, 16);
    if (lane < 16)
        *(float2*)(acc_out + (size_t)bq * 256 + h * 32 + ch) = acc2;
}

// ---------------------------------------------------------------------------
// Launch
// ---------------------------------------------------------------------------
extern "C" void kernel_launch(void* const* d_in, const int* in_sizes, int n_in,
                              void* d_out, int out_size)
{
    const float* query = (const float*)d_in[0];   // [8,1024,256]
    const float* refp  = (const float*)d_in[1];   // [8,1024,4,2]
    const float* value = (const float*)d_in[2];   // [8,13294,256]
    // d_in[3] = value_spatial_shapes (compile-time constant)
    const float* so_w  = (const float*)d_in[4];   // [256,256]  [K,N]
    const float* so_b  = (const float*)d_in[5];
    const float* aw_w  = (const float*)d_in[6];   // [256,128]  [K,N]
    const float* aw_b  = (const float*)d_in[7];
    const float* vp_w  = (const float*)d_in[8];   // [256,256]  [K,N]
    const float* vp_b  = (const float*)d_in[9];
    const float* op_w  = (const float*)d_in[10];  // [256,256]  [K,N]
    const float* op_b  = (const float*)d_in[11];
    float* out = (float*)d_out;                   // [8,1024,256]

    float* scratch = nullptr;
    cudaGetSymbolAddress((void**)&scratch, g_scratch);
    float* sV    = scratch + cfg::OFF_V;
    float* sSOAW = scratch + cfg::OFF_SOAW;
    float* sACC  = scratch + cfg::OFF_ACC;

    const int MQ = cfg::B * cfg::LQ;      // 8192
    const int MV = cfg::B * cfg::LV;      // 106352

    // 1) v = value @ vp_w + vp_b
    tf32_gemm_dual<<<dim3(2, (MV + 127) / 128), 256>>>(
        value, vp_w, 256, vp_w, 256, 256, vp_b, vp_b, sV, MV, 256, 256);
    // 2) soaw = query @ [so_w | aw_w] + [so_b | aw_b]  (split at col 256)
    tf32_gemm_dual<<<dim3(3, MQ / 128), 256>>>(
        query, so_w, 256, aw_w, 128, 256, so_b, aw_b, sSOAW, MQ, 384, 256);
    // 3) sampling (softmax folded in; geometry broadcast, branch-free)
    {
        int warps = cfg::B * cfg::LQ * cfg::H;   // 65536
        sample_kernel<<<warps / 8, 256>>>(refp, sV, sSOAW, sACC);
    }
    // 4) out = ACC @ op_w + op_b
    tf32_gemm_dual<<<dim3(2, MQ / 128), 256>>>(
        sACC, op_w, 256, op_w, 256, 256, op_b, op_b, out, MQ, 256, 256);
}